// round 16
// baseline (speedup 1.0000x reference)
#include <cuda_runtime.h>
#include <cstdint>
#include <cstddef>

#define RR 8
#define NN 300000
#define DD 128
#define AA 64
#define H_SLOT 2048            // u32 words: 128 rows x 16 bf16x2 words
#define W_SLOT 1024            // u32 words: 64 rows x 16 bf16x2 words
#define NCH 32                 // 8 relations x 4 k-chunks (32 k each)
#define LOG2E 1.4426950408889634f

// pre-swizzled bf16 W1 images, one 4KB image per (relation, k-chunk)
__device__ uint32_t g_wimg[RR * 4 * W_SLOT];

__device__ __forceinline__ float fast_sigmoid(float x) {
    float t;
    asm("tanh.approx.f32 %0, %1;" : "=f"(t) : "f"(0.5f * x));
    return fmaf(t, 0.5f, 0.5f);
}
__device__ __forceinline__ float fast_exp(float x) {
    float e; asm("ex2.approx.f32 %0, %1;" : "=f"(e) : "f"(LOG2E * x));
    return e;
}

__device__ __forceinline__ void mma_bf16_16n8k16(float c[4],
                                                 const unsigned a[4],
                                                 unsigned b0, unsigned b1) {
    asm volatile(
        "mma.sync.aligned.m16n8k16.row.col.f32.bf16.bf16.f32 "
        "{%0,%1,%2,%3}, {%4,%5,%6,%7}, {%8,%9}, {%0,%1,%2,%3};"
        : "+f"(c[0]), "+f"(c[1]), "+f"(c[2]), "+f"(c[3])
        : "r"(a[0]), "r"(a[1]), "r"(a[2]), "r"(a[3]), "r"(b0), "r"(b1));
}

__device__ __forceinline__ uint32_t pack_bf16x2(float lo, float hi) {
    uint32_t p;
    asm("cvt.rn.bf16x2.f32 %0, %1, %2;" : "=r"(p) : "f"(hi), "f"(lo));
    return p;
}

__device__ __forceinline__ void cp_async16_s(uint32_t dst, const void* src) {
    asm volatile("cp.async.cg.shared.global [%0], [%1], 16;"
                 :: "r"(dst), "l"(src));
}
#define CP_COMMIT() asm volatile("cp.async.commit_group;")
#define CP_WAIT(n)  asm volatile("cp.async.wait_group %0;" :: "n"(n))

__device__ __forceinline__ void sts64(uint32_t addr, uint32_t p0, uint32_t p1) {
    asm volatile("st.shared.v2.b32 [%0], {%1,%2};"
                 :: "r"(addr), "r"(p0), "r"(p1) : "memory");
}

__device__ __forceinline__ float4 ldcs4(const float4* p) {
    float4 v;
    asm volatile("ld.global.cs.v4.f32 {%0,%1,%2,%3}, [%4];"
                 : "=f"(v.x), "=f"(v.y), "=f"(v.z), "=f"(v.w) : "l"(p));
    return v;
}
__device__ __forceinline__ void stcs4(float4* p, float4 v) {
    asm volatile("st.global.cs.v4.f32 [%0], {%1,%2,%3,%4};"
                 :: "l"(p), "f"(v.x), "f"(v.y), "f"(v.z), "f"(v.w));
}

__device__ __forceinline__ uint32_t smem_u32(const void* p) {
    uint32_t a;
    asm("{ .reg .u64 t; cvta.to.shared.u64 t, %1; cvt.u32.u64 %0, t; }"
        : "=r"(a) : "l"(p));
    return a;
}

// swizzle lut: rows (x = (row>>1)&3) -> {0,6,10,12}
// distinct in bits{2,3} (fragment conflict freedom) AND bits{1,2} with
// bit3-free spacing (STS.64 conflict freedom)
__device__ __forceinline__ int swz(int x) {
    return ((x & 1) * 6) ^ ((x & 2) * 5);
}

// ---------- prep: convert + swizzle W1 into bf16 chunk images ----------
__global__ void prep_w(const float* __restrict__ w1) {
    int idx = blockIdx.x * 256 + threadIdx.x;
    if (idx >= RR * 4 * W_SLOT) return;
    int r  = idx >> 12;
    int kc = (idx >> 10) & 3;
    int n  = (idx >> 4) & 63;
    int j  = idx & 15;
    int sw = swz((n >> 1) & 3);
    float lo = w1[(size_t)(r * DD + kc * 32 + 2 * j) * AA + n];
    float hi = w1[(size_t)(r * DD + kc * 32 + 2 * j + 1) * AA + n];
    g_wimg[(r * 4 + kc) * W_SLOT + n * 16 + (j ^ sw)] = pack_bf16x2(lo, hi);
}

// ---------- fused main kernel ----------
__global__ void __launch_bounds__(256, 3)
fused_kernel(const float* __restrict__ h,
             const float* __restrict__ w2,
             float* __restrict__ out) {
    extern __shared__ uint32_t smemu[];
    uint32_t* sh_h  = smemu;                          // 2 * H_SLOT
    uint32_t* sh_wB = smemu + 2 * H_SLOT;             // 2 * W_SLOT
    float* sh_w2  = (float*)(smemu + 2 * H_SLOT + 2 * W_SLOT);  // 512
    float* sh_sc  = sh_w2 + RR * AA;                  // 8 * 128
    float* sh_prt = sh_sc + RR * 128;                 // 2 * 128

    const int tid = threadIdx.x;
    const long node0 = (long)blockIdx.x * 128;

    sh_w2[tid] = w2[tid];
    sh_w2[tid + 256] = w2[tid + 256];

    // ---- staging constants: one thread = one row-half (16 floats) ----
    const int srow = tid >> 1, shf = tid & 1;
    long snode = node0 + srow;
    if (snode >= NN) snode = NN - 1;                  // clamp (boundary block only)
    const float* hsrc0 = h + (size_t)snode * DD + shf * 16;
    const int ssw = swz((srow >> 1) & 3);
    const uint32_t hB = smem_u32(sh_h);
    uint32_t sdst[4];
    #pragma unroll
    for (int u = 0; u < 4; u++)
        sdst[u] = hB + (uint32_t)(srow * 16 + ((8 * shf + 2 * u) ^ ssw)) * 4;
    const uint32_t wBB = smem_u32(sh_wB);
    const uint32_t wdst = wBB + tid * 16;

    const size_t NND = (size_t)NN * DD;

    // ---- prologue: stage chunk 0 (h: LDG+cvt+STS; W: cp.async image) ----
    {
        float4 v[4];
        #pragma unroll
        for (int u = 0; u < 4; u++) v[u] = ((const float4*)hsrc0)[u];
        #pragma unroll
        for (int u = 0; u < 4; u++)
            sts64(sdst[u], pack_bf16x2(v[u].x, v[u].y), pack_bf16x2(v[u].z, v[u].w));
        cp_async16_s(wdst, g_wimg + tid * 4);
        CP_COMMIT();
    }

    const int w = tid >> 5, lane = tid & 31;
    const int g = lane >> 2, tg = lane & 3;
    const int m0 = (w & 3) * 32;   // 4-way m split
    const int nh = w >> 2;         // 2-way n split
    const int fsw = swz((g >> 1) & 3);   // fragment swizzle (same for A and B rows)

    float acc[2][4][4];

    for (int c = 0; c < NCH; c++) {
        const int kc = c & 3;

        CP_WAIT(0);        // W image for chunk c landed
        __syncthreads();   // publish h slot c&1 (STS) + W slot; order prior epoch

        // lag-1 score write for relation (c-1)/4
        if (c >= 1 && kc == 0 && tid < 128)
            sh_sc[((c - 1) >> 2) * 128 + tid] = sh_prt[tid] + sh_prt[128 + tid];

        if (kc == 0) {
            #pragma unroll
            for (int mt = 0; mt < 2; mt++)
                #pragma unroll
                for (int nt = 0; nt < 4; nt++)
                    #pragma unroll
                    for (int q = 0; q < 4; q++) acc[mt][nt][q] = 0.f;
        }

        const uint32_t* hh = sh_h + (c & 1) * H_SLOT;
        const uint32_t* ww = sh_wB + (c & 1) * W_SLOT;

        // prefetch next chunk's h into registers (LDG latency covered by MMA)
        const bool do_stage = (c + 1 < NCH);
        float4 v0, v1, v2, v3;
        if (do_stage) {
            int cn = c + 1;
            const float4* hsrc = (const float4*)(hsrc0 + (size_t)(cn >> 2) * NND
                                                 + (cn & 3) * 32);
            v0 = hsrc[0]; v1 = hsrc[1]; v2 = hsrc[2]; v3 = hsrc[3];
        }

        #pragma unroll
        for (int ks = 0; ks < 2; ks++) {
            const int c0 = (ks * 8 + tg) ^ fsw;
            const int c1 = (ks * 8 + tg + 4) ^ fsw;
            unsigned a[2][4];
            #pragma unroll
            for (int mt = 0; mt < 2; mt++) {
                int row = m0 + mt * 16 + g;
                a[mt][0] = hh[row * 16 + c0];
                a[mt][1] = hh[(row + 8) * 16 + c0];
                a[mt][2] = hh[row * 16 + c1];
                a[mt][3] = hh[(row + 8) * 16 + c1];
            }
            #pragma unroll
            for (int nt = 0; nt < 4; nt++) {
                int nr = nh * 32 + nt * 8 + g;
                unsigned b0 = ww[nr * 16 + c0];
                unsigned b1 = ww[nr * 16 + c1];
                mma_bf16_16n8k16(acc[0][nt], a[0], b0, b1);
                mma_bf16_16n8k16(acc[1][nt], a[1], b0, b1);
            }
        }

        // convert + store next chunk's h; launch its W image copy
        if (do_stage) {
            const uint32_t sb = ((c + 1) & 1) * H_SLOT * 4;
            sts64(sdst[0] + sb, pack_bf16x2(v0.x, v0.y), pack_bf16x2(v0.z, v0.w));
            sts64(sdst[1] + sb, pack_bf16x2(v1.x, v1.y), pack_bf16x2(v1.z, v1.w));
            sts64(sdst[2] + sb, pack_bf16x2(v2.x, v2.y), pack_bf16x2(v2.z, v2.w));
            sts64(sdst[3] + sb, pack_bf16x2(v3.x, v3.y), pack_bf16x2(v3.z, v3.w));
            cp_async16_s(wdst + ((c + 1) & 1) * W_SLOT * 4,
                         g_wimg + (c + 1) * W_SLOT + tid * 4);
            CP_COMMIT();
        }

        if (kc == 3) {
            const int r = c >> 2;
            float slo[2] = {0.f, 0.f}, shi[2] = {0.f, 0.f};
            #pragma unroll
            for (int mt = 0; mt < 2; mt++)
                #pragma unroll
                for (int nt = 0; nt < 4; nt++) {
                    int cb = nh * 32 + nt * 8 + 2 * tg;
                    float wa = sh_w2[r * AA + cb], wb2 = sh_w2[r * AA + cb + 1];
                    slo[mt] += fast_sigmoid(acc[mt][nt][0]) * wa + fast_sigmoid(acc[mt][nt][1]) * wb2;
                    shi[mt] += fast_sigmoid(acc[mt][nt][2]) * wa + fast_sigmoid(acc[mt][nt][3]) * wb2;
                }
            #pragma unroll
            for (int o = 1; o < 4; o <<= 1) {
                slo[0] += __shfl_xor_sync(0xffffffffu, slo[0], o);
                slo[1] += __shfl_xor_sync(0xffffffffu, slo[1], o);
                shi[0] += __shfl_xor_sync(0xffffffffu, shi[0], o);
                shi[1] += __shfl_xor_sync(0xffffffffu, shi[1], o);
            }
            if (tg == 0) {
                #pragma unroll
                for (int mt = 0; mt < 2; mt++) {
                    sh_prt[nh * 128 + m0 + mt * 16 + g]     = slo[mt];
                    sh_prt[nh * 128 + m0 + mt * 16 + g + 8] = shi[mt];
                }
            }
        }
    }
    __syncthreads();   // prt for r=7 complete

    // final score (r=7) + softmax over relations
    if (tid < 128) {
        float sv[RR];
        sv[7] = sh_prt[tid] + sh_prt[128 + tid];
        float m = sv[7];
        #pragma unroll
        for (int r = 0; r < 7; r++) { sv[r] = sh_sc[r * 128 + tid]; m = fmaxf(m, sv[r]); }
        float sum = 0.f;
        #pragma unroll
        for (int r = 0; r < RR; r++) { sv[r] = fast_exp(sv[r] - m); sum += sv[r]; }
        float inv = 1.f / sum;
        #pragma unroll
        for (int r = 0; r < RR; r++) sh_sc[r * 128 + tid] = sv[r] * inv;
    }
    __syncthreads();

    // phase 3: weighted sum, all fp32 from global (reversed order: newest-staged
    // relations are L2-hot), .cs to avoid polluting L2 for other CTAs
    const float4* hp = (const float4*)h;
    float4* op = (float4*)out;
    #pragma unroll 4
    for (int i = 0; i < 16; i++) {
        int idx = tid + i * 256;
        int nrow = idx >> 5, c4 = idx & 31;
        long node = node0 + nrow;
        if (node >= NN) continue;

        float a[RR];
        #pragma unroll
        for (int r = 0; r < RR; r++) a[r] = sh_sc[r * 128 + nrow];

        float4 acc4 = make_float4(0.f, 0.f, 0.f, 0.f);
        #pragma unroll
        for (int r = 7; r >= 0; r--) {
            float4 v = ldcs4(&hp[((size_t)r * NN + node) * 32 + c4]);
            acc4.x += a[r] * v.x; acc4.y += a[r] * v.y;
            acc4.z += a[r] * v.z; acc4.w += a[r] * v.w;
        }
        stcs4(&op[(size_t)node * 32 + c4], acc4);
    }
}

extern "C" void kernel_launch(void* const* d_in, const int* in_sizes, int n_in,
                              void* d_out, int out_size) {
    const float* h  = (const float*)d_in[0];
    const float* w1 = (const float*)d_in[1];
    const float* w2 = (const float*)d_in[2];
    float* out = (float*)d_out;

    const int smem_bytes =
        (2 * H_SLOT + 2 * W_SLOT + RR * AA + RR * 128 + 2 * 128) * 4;  // 31,744 B
    cudaFuncSetAttribute(fused_kernel,
                         cudaFuncAttributeMaxDynamicSharedMemorySize, smem_bytes);

    prep_w<<<(RR * 4 * W_SLOT + 255) / 256, 256>>>(w1);

    const int grid = (NN + 127) / 128;   // 2344
    fused_kernel<<<grid, 256, smem_bytes>>>(h, w2, out);
}

// round 17
// speedup vs baseline: 1.2684x; 1.2684x over previous
#include <cuda_runtime.h>
#include <cstdint>
#include <cstddef>

#define RR 8
#define NN 300000
#define DD 128
#define AA 64
#define TILE_M 128
#define HCH 36                 // h chunk row stride (32+4): frag banks 4g+tg distinct
#define WCH 72                 // w1 row stride (64+8): frag banks 8tg+g distinct
#define H_SLOT (TILE_M * HCH)  // 4608 floats
#define W_SLOT (32 * WCH)      // 2304 floats
#define NCH 32                 // 8 relations x 4 k-chunks
#define LOG2E 1.4426950408889634f

__device__ __forceinline__ float fast_sigmoid(float x) {
    float t;
    asm("tanh.approx.f32 %0, %1;" : "=f"(t) : "f"(0.5f * x));
    return fmaf(t, 0.5f, 0.5f);
}
__device__ __forceinline__ float fast_exp(float x) {
    float e; asm("ex2.approx.f32 %0, %1;" : "=f"(e) : "f"(LOG2E * x));
    return e;
}

__device__ __forceinline__ void mma_tf32_16n8k8(float c[4],
                                                const unsigned a[4],
                                                unsigned b0, unsigned b1) {
    asm volatile(
        "mma.sync.aligned.m16n8k8.row.col.f32.tf32.tf32.f32 "
        "{%0,%1,%2,%3}, {%4,%5,%6,%7}, {%8,%9}, {%0,%1,%2,%3};"
        : "+f"(c[0]), "+f"(c[1]), "+f"(c[2]), "+f"(c[3])
        : "r"(a[0]), "r"(a[1]), "r"(a[2]), "r"(a[3]), "r"(b0), "r"(b1));
}

__device__ __forceinline__ void cp_async16_s(uint32_t dst, const float* src) {
    asm volatile("cp.async.cg.shared.global [%0], [%1], 16;"
                 :: "r"(dst), "l"(src));
}
#define CP_COMMIT() asm volatile("cp.async.commit_group;")
#define CP_WAIT(n)  asm volatile("cp.async.wait_group %0;" :: "n"(n))

__device__ __forceinline__ float4 ldcs4(const float4* p) {
    float4 v;
    asm volatile("ld.global.cs.v4.f32 {%0,%1,%2,%3}, [%4];"
                 : "=f"(v.x), "=f"(v.y), "=f"(v.z), "=f"(v.w) : "l"(p));
    return v;
}
__device__ __forceinline__ void stcs4(float4* p, float4 v) {
    asm volatile("st.global.cs.v4.f32 [%0], {%1,%2,%3,%4};"
                 :: "l"(p), "f"(v.x), "f"(v.y), "f"(v.z), "f"(v.w));
}

__device__ __forceinline__ uint32_t smem_u32(const void* p) {
    uint32_t a;
    asm("{ .reg .u64 t; cvta.to.shared.u64 t, %1; cvt.u32.u64 %0, t; }"
        : "=r"(a) : "l"(p));
    return a;
}

__global__ void __launch_bounds__(256, 3)
fused_kernel(const float* __restrict__ h,
             const float* __restrict__ w1,
             const float* __restrict__ w2,
             float* __restrict__ out) {
    extern __shared__ float smem[];
    float* sh_h   = smem;                       // 2 * H_SLOT
    float* sh_w   = sh_h + 2 * H_SLOT;          // 2 * W_SLOT
    float* sh_w2  = sh_w + 2 * W_SLOT;          // 512
    float* sh_sc  = sh_w2 + RR * AA;            // 8 * 128
    float* sh_prt = sh_sc + RR * TILE_M;        // 2 planes x 128

    const int tid = threadIdx.x;
    const long node0 = (long)blockIdx.x * TILE_M;
    const bool boundary = (node0 + TILE_M > NN);   // true for 1 block only

    sh_w2[tid] = w2[tid];
    sh_w2[tid + 256] = w2[tid + 256];

    // ---- per-thread staging constants (clamped addressing) ----
    const int hrow0 = tid >> 3, hc4 = tid & 7;
    const size_t hoff0 = (size_t)(node0 + hrow0) * DD + hc4 * 4;
    const uint32_t hB = smem_u32(sh_h);
    const uint32_t hdst0 = hB + (uint32_t)(hrow0 * HCH + hc4 * 4) * 4;
    const int wrow0 = tid >> 4, wc4 = tid & 15;
    const size_t woff0 = (size_t)wrow0 * AA + wc4 * 4;
    const uint32_t wB = smem_u32(sh_w);
    const uint32_t wdst0 = wB + (uint32_t)(wrow0 * WCH + wc4 * 4) * 4;

    const size_t NND = (size_t)NN * DD;

    // per-piece global h offset (clamped only in the boundary block)
    auto h_off = [&](int i) -> size_t {
        if (!boundary) return hoff0 + (size_t)i * (32 * DD);
        long node = node0 + hrow0 + i * 32;
        if (node >= NN) node = NN - 1;
        return (size_t)node * DD + hc4 * 4;
    };

    // prologue: stage chunk 0
    {
        const float* hs = h;                       // r=0, kc=0
        const float* ws = w1;
        #pragma unroll
        for (int i = 0; i < 4; i++)
            cp_async16_s(hdst0 + i * (32 * HCH * 4), hs + h_off(i));
        #pragma unroll
        for (int i = 0; i < 2; i++)
            cp_async16_s(wdst0 + i * (16 * WCH * 4), ws + woff0 + i * (16 * AA));
        CP_COMMIT();
    }

    const int w = tid >> 5, lane = tid & 31;
    const int g = lane >> 2, tg = lane & 3;
    const int m0 = (w & 3) * 32;   // 4-way m split
    const int nh = w >> 2;         // 2-way n split

    float acc[2][4][4];

    for (int c = 0; c < NCH; c++) {
        const int kc = c & 3;

        CP_WAIT(0);        // group for chunk c (committed during iter c-1) landed
        __syncthreads();   // publish slot c&1; all prior reads/writes ordered

        // lag-1 score write: relation (c-1)/4 finished its epilogue in iter c-1
        if (c >= 1 && (c & 3) == 0 && tid < TILE_M)
            sh_sc[((c - 1) >> 2) * TILE_M + tid] = sh_prt[tid] + sh_prt[TILE_M + tid];

        if (kc == 0) {
            #pragma unroll
            for (int mt = 0; mt < 2; mt++)
                #pragma unroll
                for (int nt = 0; nt < 4; nt++)
                    #pragma unroll
                    for (int q = 0; q < 4; q++) acc[mt][nt][q] = 0.f;
        }

        const unsigned* hh = (const unsigned*)(sh_h + (c & 1) * H_SLOT);
        const unsigned* ww = (const unsigned*)(sh_w + (c & 1) * W_SLOT);

        // next-chunk staging bases (hoisted out of the piece loop)
        const bool do_stage = (c + 1 < NCH);
        const float* hsn = nullptr; const float* wsn = nullptr;
        uint32_t hdn = 0, wdn = 0;
        if (do_stage) {
            int cn = c + 1;
            hsn = h + (size_t)(cn >> 2) * NND + (cn & 3) * 32;
            wsn = w1 + (size_t)(cn >> 2) * (DD * AA) + (cn & 3) * (32 * AA);
            hdn = hdst0 + (uint32_t)((cn & 1) * H_SLOT * 4);
            wdn = wdst0 + (uint32_t)((cn & 1) * W_SLOT * 4);
        }

        #pragma unroll
        for (int kt = 0; kt < 4; kt++) {
            // de-burst staging of chunk c+1
            if (do_stage) {
                if (kt < 2) {
                    cp_async16_s(hdn + (2 * kt) * (32 * HCH * 4), hsn + h_off(2 * kt));
                    cp_async16_s(hdn + (2 * kt + 1) * (32 * HCH * 4), hsn + h_off(2 * kt + 1));
                } else if (kt == 2) {
                    cp_async16_s(wdn, wsn + woff0);
                    cp_async16_s(wdn + 16 * WCH * 4, wsn + woff0 + 16 * AA);
                    CP_COMMIT();
                }
            }
            unsigned a[2][4];
            #pragma unroll
            for (int mt = 0; mt < 2; mt++) {
                int row = m0 + mt * 16 + g;
                int col = kt * 8 + tg;
                a[mt][0] = hh[row * HCH + col];
                a[mt][1] = hh[(row + 8) * HCH + col];
                a[mt][2] = hh[row * HCH + col + 4];
                a[mt][3] = hh[(row + 8) * HCH + col + 4];
            }
            #pragma unroll
            for (int nt = 0; nt < 4; nt++) {
                int nb = nh * 32 + nt * 8;
                unsigned b0 = ww[(kt * 8 + tg) * WCH + nb + g];
                unsigned b1 = ww[(kt * 8 + tg + 4) * WCH + nb + g];
                mma_tf32_16n8k8(acc[0][nt], a[0], b0, b1);
                mma_tf32_16n8k8(acc[1][nt], a[1], b0, b1);
            }
        }

        if (kc == 3) {
            const int r = c >> 2;
            float slo[2] = {0.f, 0.f}, shi[2] = {0.f, 0.f};
            #pragma unroll
            for (int mt = 0; mt < 2; mt++)
                #pragma unroll
                for (int nt = 0; nt < 4; nt++) {
                    int cb = nh * 32 + nt * 8 + 2 * tg;
                    float wa = sh_w2[r * AA + cb], wb2 = sh_w2[r * AA + cb + 1];
                    slo[mt] += fast_sigmoid(acc[mt][nt][0]) * wa + fast_sigmoid(acc[mt][nt][1]) * wb2;
                    shi[mt] += fast_sigmoid(acc[mt][nt][2]) * wa + fast_sigmoid(acc[mt][nt][3]) * wb2;
                }
            #pragma unroll
            for (int o = 1; o < 4; o <<= 1) {
                slo[0] += __shfl_xor_sync(0xffffffffu, slo[0], o);
                slo[1] += __shfl_xor_sync(0xffffffffu, slo[1], o);
                shi[0] += __shfl_xor_sync(0xffffffffu, shi[0], o);
                shi[1] += __shfl_xor_sync(0xffffffffu, shi[1], o);
            }
            if (tg == 0) {
                #pragma unroll
                for (int mt = 0; mt < 2; mt++) {
                    sh_prt[nh * TILE_M + m0 + mt * 16 + g]     = slo[mt];
                    sh_prt[nh * TILE_M + m0 + mt * 16 + g + 8] = shi[mt];
                }
            }
        }
    }
    __syncthreads();   // prt for r=7 complete; ring slots final

    // final score (r=7) + softmax over relations
    if (tid < TILE_M) {
        float sv[RR];
        sv[7] = sh_prt[tid] + sh_prt[TILE_M + tid];
        float m = sv[7];
        #pragma unroll
        for (int r = 0; r < 7; r++) { sv[r] = sh_sc[r * TILE_M + tid]; m = fmaxf(m, sv[r]); }
        float sum = 0.f;
        #pragma unroll
        for (int r = 0; r < RR; r++) { sv[r] = fast_exp(sv[r] - m); sum += sv[r]; }
        float inv = 1.f / sum;
        #pragma unroll
        for (int r = 0; r < RR; r++) sh_sc[r * TILE_M + tid] = sv[r] * inv;
    }
    __syncthreads();

    // phase 3: weighted sum. r=7 cols 64..127 from the smem ring
    // (slot0 = chunk30 = k[64:96), slot1 = chunk31 = k[96:128)); rest via .cs.
    const float4* hp = (const float4*)h;
    float4* op = (float4*)out;
    #pragma unroll 4
    for (int i = 0; i < 16; i++) {
        int idx = tid + i * 256;
        int nrow = idx >> 5, c4 = idx & 31;
        long node = node0 + nrow;
        if (node >= NN) continue;

        float a[RR];
        #pragma unroll
        for (int r = 0; r < RR; r++) a[r] = sh_sc[r * TILE_M + nrow];

        float4 acc4;
        {
            float4 v;
            if (c4 < 16) {
                v = ldcs4(&hp[((size_t)7 * NN + node) * 32 + c4]);
            } else {
                const float* sp = sh_h + ((c4 >> 3) & 1) * H_SLOT
                                + nrow * HCH + (c4 & 7) * 4;
                v = *(const float4*)sp;
            }
            acc4.x = a[7] * v.x; acc4.y = a[7] * v.y;
            acc4.z = a[7] * v.z; acc4.w = a[7] * v.w;
        }
        #pragma unroll
        for (int r = 6; r >= 0; r--) {
            float4 v = ldcs4(&hp[((size_t)r * NN + node) * 32 + c4]);
            acc4.x += a[r] * v.x; acc4.y += a[r] * v.y;
            acc4.z += a[r] * v.z; acc4.w += a[r] * v.w;
        }
        stcs4(&op[(size_t)node * 32 + c4], acc4);
    }
}

extern "C" void kernel_launch(void* const* d_in, const int* in_sizes, int n_in,
                              void* d_out, int out_size) {
    const float* h  = (const float*)d_in[0];
    const float* w1 = (const float*)d_in[1];
    const float* w2 = (const float*)d_in[2];
    float* out = (float*)d_out;

    const int smem_bytes =
        (2 * H_SLOT + 2 * W_SLOT + RR * AA + RR * TILE_M + 2 * TILE_M) * 4;  // ~61 KB
    cudaFuncSetAttribute(fused_kernel,
                         cudaFuncAttributeMaxDynamicSharedMemorySize, smem_bytes);

    dim3 grid((NN + TILE_M - 1) / TILE_M);
    fused_kernel<<<grid, 256, smem_bytes>>>(h, w1, w2, out);
}